// round 3
// baseline (speedup 1.0000x reference)
#include <cuda_runtime.h>

// RelationalPolicyHead: probs = softmax( relu( [emb[src]||emb[tgt]] @ W1 + b1 ) @ W2 + b2 )
// E = 1e6 edges, H = 128.  legal_moves arrives as INT32 (JAX x64 disabled), layout [2, E].
//
// K1: fused gather + GEMM -> logits (FMA-bound, W1 in smem, A-tiles double buffered)
// K2: partial sums of exp(logit)   (no max-sub: logits bounded ~|6|)
// K3: final reduce -> 1/total
// K4: probs = exp(logit) * invTotal

#define BM 256
#define BN 128
#define BK 32
#define THREADS 512
#define RED_BLOCKS 1024

__device__ float g_logits[1048576];
__device__ float g_partials[RED_BLOCKS];
__device__ float g_inv_total;

// dynamic smem layout (floats):
//  [0, 32768)            W1s  [256][128]
//  [32768, 49152)        As   [2][32][256]   (transposed: As[k][m])
//  [49152, 49280)        b1s  [128]
//  [49280, 49408)        W2s  [128]
//  [49408, 49920)        idx  [512] ints (src[256], tgt[256])
#define SMEM_FLOATS 49920
#define SMEM_BYTES (SMEM_FLOATS * 4)

__global__ __launch_bounds__(THREADS, 1)
void k_gemm(const float* __restrict__ emb, const int* __restrict__ lm,
            const float* __restrict__ W1, const float* __restrict__ b1,
            const float* __restrict__ W2, const float* __restrict__ b2,
            int E) {
    extern __shared__ float sm[];
    float* W1s = sm;
    float* As  = sm + 32768;
    float* b1s = sm + 49152;
    float* W2s = sm + 49280;
    int*   idx = (int*)(sm + 49408);

    const int tid = threadIdx.x;
    const int e0  = blockIdx.x * BM;
    const int cnt = min(BM, E - e0);

    // ---- load W1 (32768 floats = 8192 float4, 16 per thread) ----
    {
        const float4* srcp = (const float4*)W1;
        float4* dstp = (float4*)W1s;
        #pragma unroll
        for (int i = 0; i < 16; i++) dstp[tid + i * THREADS] = srcp[tid + i * THREADS];
    }
    if (tid < 128) { b1s[tid] = b1[tid]; W2s[tid] = W2[tid]; }
    if (tid < BM) {
        int s = 0, t = 0;
        if (tid < cnt) {
            s = lm[e0 + tid];
            t = lm[E + e0 + tid];
        }
        idx[tid]      = s;
        idx[BM + tid] = t;
    }
    __syncthreads();

    const int gm    = tid >> 1;   // gather row 0..255
    const int gpart = tid & 1;    // half of 32-feature strip

    float4 pre[4];

    // ---- prologue: gather K-tile 0 (features 0..31 of src) ----
    {
        int node = idx[gm];
        const float4* p = (const float4*)(emb + (size_t)node * 128 + gpart * 16);
        #pragma unroll
        for (int j = 0; j < 4; j++) pre[j] = p[j];
        #pragma unroll
        for (int j = 0; j < 4; j++) {
            int kl = gpart * 16 + j * 4;
            As[(kl + 0) * BM + gm] = pre[j].x;
            As[(kl + 1) * BM + gm] = pre[j].y;
            As[(kl + 2) * BM + gm] = pre[j].z;
            As[(kl + 3) * BM + gm] = pre[j].w;
        }
    }
    __syncthreads();

    const int tn8 = (tid & 15) * 8;
    const int tm8 = (tid >> 4) * 8;

    float acc[8][8];
    #pragma unroll
    for (int i = 0; i < 8; i++)
        #pragma unroll
        for (int j = 0; j < 8; j++) acc[i][j] = 0.f;

    // ---- main loop over 8 K-tiles ----
    for (int kk = 0; kk < 8; kk++) {
        if (kk < 7) {
            const int kkn = kk + 1;
            const int node  = idx[(kkn >= 4 ? BM : 0) + gm];
            const int fbase = (kkn * 32) & 127;
            const float4* p = (const float4*)(emb + (size_t)node * 128 + fbase + gpart * 16);
            #pragma unroll
            for (int j = 0; j < 4; j++) pre[j] = p[j];
        }

        const float* buf = As + (kk & 1) * (BK * BM);
        const float* wk  = W1s + kk * BK * 128;

        #pragma unroll 4
        for (int k = 0; k < BK; k++) {
            float4 a0 = *(const float4*)(buf + k * BM + tm8);
            float4 a1 = *(const float4*)(buf + k * BM + tm8 + 4);
            float4 w0 = *(const float4*)(wk + k * 128 + tn8);
            float4 w1 = *(const float4*)(wk + k * 128 + tn8 + 4);
            float av[8] = {a0.x, a0.y, a0.z, a0.w, a1.x, a1.y, a1.z, a1.w};
            float bv[8] = {w0.x, w0.y, w0.z, w0.w, w1.x, w1.y, w1.z, w1.w};
            #pragma unroll
            for (int i = 0; i < 8; i++)
                #pragma unroll
                for (int j = 0; j < 8; j++)
                    acc[i][j] = fmaf(av[i], bv[j], acc[i][j]);
        }
        __syncthreads();

        if (kk < 7) {
            float* buf2 = As + ((kk + 1) & 1) * (BK * BM);
            #pragma unroll
            for (int j = 0; j < 4; j++) {
                int kl = gpart * 16 + j * 4;
                buf2[(kl + 0) * BM + gm] = pre[j].x;
                buf2[(kl + 1) * BM + gm] = pre[j].y;
                buf2[(kl + 2) * BM + gm] = pre[j].z;
                buf2[(kl + 3) * BM + gm] = pre[j].w;
            }
            __syncthreads();
        }
    }

    // ---- epilogue: bias + relu + W2 dot, reduce across 16 column-threads ----
    float* red = As;  // reuse as [16][256]
    {
        #pragma unroll
        for (int i = 0; i < 8; i++) {
            float p = 0.f;
            #pragma unroll
            for (int j = 0; j < 8; j++) {
                float h = acc[i][j] + b1s[tn8 + j];
                h = fmaxf(h, 0.f);
                p = fmaf(h, W2s[tn8 + j], p);
            }
            red[(tid & 15) * BM + tm8 + i] = p;
        }
    }
    __syncthreads();
    if (tid < cnt) {
        float s = b2[0];
        #pragma unroll
        for (int t = 0; t < 16; t++) s += red[t * BM + tid];
        g_logits[e0 + tid] = s;
    }
}

__global__ void k_sumexp(int E) {
    __shared__ float sdata[256];
    float s = 0.f;
    for (int i = blockIdx.x * 256 + threadIdx.x; i < E; i += RED_BLOCKS * 256)
        s += expf(g_logits[i]);
    sdata[threadIdx.x] = s;
    __syncthreads();
    for (int o = 128; o > 0; o >>= 1) {
        if (threadIdx.x < o) sdata[threadIdx.x] += sdata[threadIdx.x + o];
        __syncthreads();
    }
    if (threadIdx.x == 0) g_partials[blockIdx.x] = sdata[0];
}

__global__ void k_final() {
    __shared__ float sdata[256];
    float s = 0.f;
    for (int i = threadIdx.x; i < RED_BLOCKS; i += 256) s += g_partials[i];
    sdata[threadIdx.x] = s;
    __syncthreads();
    for (int o = 128; o > 0; o >>= 1) {
        if (threadIdx.x < o) sdata[threadIdx.x] += sdata[threadIdx.x + o];
        __syncthreads();
    }
    if (threadIdx.x == 0) g_inv_total = 1.f / sdata[0];
}

__global__ void k_norm(float* __restrict__ out, int E) {
    int i = blockIdx.x * blockDim.x + threadIdx.x;
    if (i < E) out[i] = expf(g_logits[i]) * g_inv_total;
}

extern "C" void kernel_launch(void* const* d_in, const int* in_sizes, int n_in,
                              void* d_out, int out_size) {
    const float* emb = (const float*)d_in[0];
    const int*   lm  = (const int*)d_in[1];
    const float* W1  = (const float*)d_in[2];
    const float* b1  = (const float*)d_in[3];
    const float* W2  = (const float*)d_in[4];
    const float* b2  = (const float*)d_in[5];
    float* out = (float*)d_out;
    const int E = in_sizes[1] / 2;

    cudaFuncSetAttribute(k_gemm, cudaFuncAttributeMaxDynamicSharedMemorySize, SMEM_BYTES);

    const int nb = (E + BM - 1) / BM;
    k_gemm<<<nb, THREADS, SMEM_BYTES>>>(emb, lm, W1, b1, W2, b2, E);
    k_sumexp<<<RED_BLOCKS, 256>>>(E);
    k_final<<<1, 256>>>();
    k_norm<<<(E + 255) / 256, 256>>>(out, E);
}

// round 5
// speedup vs baseline: 4.7080x; 4.7080x over previous
#include <cuda_runtime.h>
#include <cstdint>

// RelationalPolicyHead, factored:
//   W1 = [U; V]  (rows 0..127 -> src part, 128..255 -> tgt part)
//   P = emb @ U, Q = emb @ V           (per-node, 6.7 GFLOP total)
//   logit_e = W2^T relu(P[src] + Q[tgt] + b1) + b2   (per-edge, cheap)
//   probs = softmax(logits)
// Exact same arithmetic as reference up to fp32 reassociation.
//
// K_node: tiled fp32 GEMM [nodes,128]@[128,128], blockIdx.y selects U/V half.
// K_edge: warp per edge; lane-coalesced float4 reads of P/Q rows; shfl reduce.
// K2/K3/K4: deterministic softmax tail.

#define RED_BLOCKS 1024
#define MAX_NODES 100000

__device__ float g_P[MAX_NODES * 128];
__device__ float g_Q[MAX_NODES * 128];
__device__ float g_logits[1048576];
__device__ float g_partials[RED_BLOCKS];
__device__ float g_inv_total;

// ---------------- node GEMM: out = emb @ W1half ----------------
// tile M=128 nodes, N=128, K=128 (one shot). 256 threads, 8x8 per thread.
#define NODE_SMEM (2 * 128 * 128 * 4)

__global__ __launch_bounds__(256, 1)
void k_node(const float* __restrict__ emb, const float* __restrict__ W1, int nodes) {
    extern __shared__ float sm[];
    float* As = sm;            // [m][k]  128x128
    float* Bs = sm + 16384;    // [k][n]  128x128

    const int tid = threadIdx.x;
    const int m0 = blockIdx.x * 128;
    const float* Bsrc = W1 + blockIdx.y * 16384;

    // load B (contiguous 64KB) and A (guarded rows), both as float4
    {
        const float4* bs4 = (const float4*)Bsrc;
        float4* Bd = (float4*)Bs;
        float4* Ad = (float4*)As;
        #pragma unroll
        for (int t = 0; t < 16; t++) {
            int i4 = t * 256 + tid;
            Bd[i4] = bs4[i4];
            int row = i4 >> 5;
            float4 v = make_float4(0.f, 0.f, 0.f, 0.f);
            if (m0 + row < nodes) v = ((const float4*)emb)[(size_t)(m0 + row) * 32 + (i4 & 31)];
            Ad[i4] = v;
        }
    }
    __syncthreads();

    const int tm8 = (tid >> 4) * 8;
    const int tn8 = (tid & 15) * 8;

    float acc[8][8];
    #pragma unroll
    for (int i = 0; i < 8; i++)
        #pragma unroll
        for (int j = 0; j < 8; j++) acc[i][j] = 0.f;

    #pragma unroll 4
    for (int k = 0; k < 128; k++) {
        float a[8];
        #pragma unroll
        for (int i = 0; i < 8; i++) a[i] = As[(tm8 + i) * 128 + k];  // broadcast (2 addrs/warp)
        float4 w0 = *(const float4*)(Bs + k * 128 + tn8);
        float4 w1 = *(const float4*)(Bs + k * 128 + tn8 + 4);
        float bv[8] = {w0.x, w0.y, w0.z, w0.w, w1.x, w1.y, w1.z, w1.w};
        #pragma unroll
        for (int i = 0; i < 8; i++)
            #pragma unroll
            for (int j = 0; j < 8; j++)
                acc[i][j] = fmaf(a[i], bv[j], acc[i][j]);
    }

    float* out = blockIdx.y ? g_Q : g_P;
    #pragma unroll
    for (int i = 0; i < 8; i++) {
        int r = m0 + tm8 + i;
        if (r < nodes) {
            float4* o = (float4*)(out + (size_t)r * 128 + tn8);
            o[0] = make_float4(acc[i][0], acc[i][1], acc[i][2], acc[i][3]);
            o[1] = make_float4(acc[i][4], acc[i][5], acc[i][6], acc[i][7]);
        }
    }
}

// ---------------- edge kernel: warp per edge ----------------
__global__ __launch_bounds__(256)
void k_edge(const int* __restrict__ lm, const float* __restrict__ b1,
            const float* __restrict__ W2, const float* __restrict__ b2, int E) {
    const int lane = threadIdx.x & 31;
    const int w    = (blockIdx.x * 256 + threadIdx.x) >> 5;
    const int nw   = (gridDim.x * 256) >> 5;

    const float4 b1v = ((const float4*)b1)[lane];
    const float4 w2v = ((const float4*)W2)[lane];
    const float  b2v = b2[0];

    for (int e = w; e < E; e += nw) {
        int s = lm[e];
        int t = lm[E + e];
        float4 pv = ((const float4*)g_P)[(size_t)s * 32 + lane];
        float4 qv = ((const float4*)g_Q)[(size_t)t * 32 + lane];
        float h0 = fmaxf(pv.x + qv.x + b1v.x, 0.f);
        float h1 = fmaxf(pv.y + qv.y + b1v.y, 0.f);
        float h2 = fmaxf(pv.z + qv.z + b1v.z, 0.f);
        float h3 = fmaxf(pv.w + qv.w + b1v.w, 0.f);
        float p = h0 * w2v.x;
        p = fmaf(h1, w2v.y, p);
        p = fmaf(h2, w2v.z, p);
        p = fmaf(h3, w2v.w, p);
        #pragma unroll
        for (int o = 16; o > 0; o >>= 1) p += __shfl_xor_sync(0xFFFFFFFFu, p, o);
        if (lane == 0) g_logits[e] = p + b2v;
    }
}

// ---------------- softmax tail ----------------
__global__ void k_sumexp(int E) {
    __shared__ float sdata[256];
    float s = 0.f;
    for (int i = blockIdx.x * 256 + threadIdx.x; i < E; i += RED_BLOCKS * 256)
        s += expf(g_logits[i]);
    sdata[threadIdx.x] = s;
    __syncthreads();
    for (int o = 128; o > 0; o >>= 1) {
        if (threadIdx.x < o) sdata[threadIdx.x] += sdata[threadIdx.x + o];
        __syncthreads();
    }
    if (threadIdx.x == 0) g_partials[blockIdx.x] = sdata[0];
}
__global__ void k_final() {
    __shared__ float sdata[256];
    float s = 0.f;
    for (int i = threadIdx.x; i < RED_BLOCKS; i += 256) s += g_partials[i];
    sdata[threadIdx.x] = s;
    __syncthreads();
    for (int o = 128; o > 0; o >>= 1) {
        if (threadIdx.x < o) sdata[threadIdx.x] += sdata[threadIdx.x + o];
        __syncthreads();
    }
    if (threadIdx.x == 0) g_inv_total = 1.f / sdata[0];
}
__global__ void k_norm(float* __restrict__ out, int E) {
    int i = blockIdx.x * blockDim.x + threadIdx.x;
    if (i < E) out[i] = expf(g_logits[i]) * g_inv_total;
}

extern "C" void kernel_launch(void* const* d_in, const int* in_sizes, int n_in,
                              void* d_out, int out_size) {
    const float* emb = (const float*)d_in[0];
    const int*   lm  = (const int*)d_in[1];
    const float* W1  = (const float*)d_in[2];
    const float* b1  = (const float*)d_in[3];
    const float* W2  = (const float*)d_in[4];
    const float* b2  = (const float*)d_in[5];
    float* out = (float*)d_out;
    const int E     = in_sizes[1] / 2;
    const int nodes = in_sizes[0] / 128;

    cudaFuncSetAttribute(k_node, cudaFuncAttributeMaxDynamicSharedMemorySize, NODE_SMEM);

    dim3 ngrid((nodes + 127) / 128, 2);
    k_node<<<ngrid, 256, NODE_SMEM>>>(emb, W1, nodes);
    k_edge<<<2048, 256>>>(lm, b1, W2, b2, E);
    k_sumexp<<<RED_BLOCKS, 256>>>(E);
    k_final<<<1, 256>>>();
    k_norm<<<(E + 255) / 256, 256>>>(out, E);
}

// round 7
// speedup vs baseline: 4.8732x; 1.0351x over previous
#include <cuda_runtime.h>
#include <cstdint>

// RelationalPolicyHead, factored + fp32x2:
//   P = emb @ U, Q = emb @ V  (U/V = halves of W1)      [k_node, FFMA2-packed]
//   e_exp = exp( W2^T relu(P[src]+Q[tgt]+b1) + b2 )      [k_edge, half-warp/edge]
//   total = sum(e_exp)  (last-block reduce)              [k_sumexp]
//   probs = e_exp * (1/total)                            [k_norm]

#define RED_BLOCKS 1024
#define MAX_NODES 100000

__device__ float g_P[MAX_NODES * 128];
__device__ float g_Q[MAX_NODES * 128];
__device__ float g_exps[1048576];
__device__ float g_partials[RED_BLOCKS];
__device__ float g_inv_total;
__device__ int   g_done = 0;

#define FMA_F32X2(d, a, b, c) \
    asm("fma.rn.f32x2 %0, %1, %2, %3;" : "=l"(d) : "l"(a), "l"(b), "l"(c))
#define DUP_F32X2(d, s) \
    asm("mov.b64 %0, {%1, %1};" : "=l"(d) : "f"(s))
#define UNPACK_F32X2(lo, hi, v) \
    asm("mov.b64 {%0, %1}, %2;" : "=f"(lo), "=f"(hi) : "l"(v))

// ---------------- node GEMM: out = emb @ W1half (FFMA2) ----------------
// tile M=128, N=128, K=128. 256 threads, each 8 rows x 8 cols (4 f32x2 pairs).
#define NODE_SMEM (2 * 128 * 128 * 4)

__global__ __launch_bounds__(256, 1)
void k_node(const float* __restrict__ emb, const float* __restrict__ W1, int nodes) {
    extern __shared__ float sm[];
    float* As = sm;            // [m][k] 128x128
    float* Bs = sm + 16384;    // [k][n] 128x128

    const int tid = threadIdx.x;
    const int m0 = blockIdx.x * 128;
    const float* Bsrc = W1 + blockIdx.y * 16384;

    {
        const float4* bs4 = (const float4*)Bsrc;
        float4* Bd = (float4*)Bs;
        float4* Ad = (float4*)As;
        #pragma unroll
        for (int t = 0; t < 16; t++) {
            int i4 = t * 256 + tid;
            Bd[i4] = bs4[i4];
            int row = i4 >> 5;
            float4 v = make_float4(0.f, 0.f, 0.f, 0.f);
            if (m0 + row < nodes) v = ((const float4*)emb)[(size_t)(m0 + row) * 32 + (i4 & 31)];
            Ad[i4] = v;
        }
    }
    __syncthreads();

    const int tm8 = (tid >> 4) * 8;
    const int tn8 = (tid & 15) * 8;

    unsigned long long acc2[8][4];
    #pragma unroll
    for (int i = 0; i < 8; i++)
        #pragma unroll
        for (int j = 0; j < 4; j++) acc2[i][j] = 0ull;

    #pragma unroll 2
    for (int k = 0; k < 128; k++) {
        unsigned long long aa[8];
        #pragma unroll
        for (int i = 0; i < 8; i++) {
            float a = As[(tm8 + i) * 128 + k];      // broadcast LDS
            DUP_F32X2(aa[i], a);
        }
        ulonglong2 bv0 = *(const ulonglong2*)(Bs + k * 128 + tn8);      // LDS.128
        ulonglong2 bv1 = *(const ulonglong2*)(Bs + k * 128 + tn8 + 4);  // LDS.128
        unsigned long long bp[4] = {bv0.x, bv0.y, bv1.x, bv1.y};
        #pragma unroll
        for (int i = 0; i < 8; i++)
            #pragma unroll
            for (int j = 0; j < 4; j++)
                FMA_F32X2(acc2[i][j], aa[i], bp[j], acc2[i][j]);
    }

    float* out = blockIdx.y ? g_Q : g_P;
    #pragma unroll
    for (int i = 0; i < 8; i++) {
        int r = m0 + tm8 + i;
        if (r < nodes) {
            float c[8];
            #pragma unroll
            for (int j = 0; j < 4; j++) UNPACK_F32X2(c[2 * j], c[2 * j + 1], acc2[i][j]);
            float4* o = (float4*)(out + (size_t)r * 128 + tn8);
            o[0] = make_float4(c[0], c[1], c[2], c[3]);
            o[1] = make_float4(c[4], c[5], c[6], c[7]);
        }
    }
}

// ---------------- edge kernel: half-warp per edge, fused exp ----------------
__global__ __launch_bounds__(256)
void k_edge(const int* __restrict__ lm, const float* __restrict__ b1,
            const float* __restrict__ W2, const float* __restrict__ b2, int E) {
    const int lane   = threadIdx.x & 31;
    const int lane16 = lane & 15;
    const int hw     = ((blockIdx.x * 256 + threadIdx.x) >> 5) * 2 + (lane >> 4);
    const int nhw    = (gridDim.x * 256) >> 4;

    const float4 b1a = ((const float4*)b1)[lane16 * 2];
    const float4 b1b = ((const float4*)b1)[lane16 * 2 + 1];
    const float4 w2a = ((const float4*)W2)[lane16 * 2];
    const float4 w2b = ((const float4*)W2)[lane16 * 2 + 1];
    const float  b2v = b2[0];

    for (int e = hw; e < E; e += nhw) {
        int s = lm[e];
        int t = lm[E + e];
        const float4* pr = (const float4*)g_P + (size_t)s * 32 + lane16 * 2;
        const float4* qr = (const float4*)g_Q + (size_t)t * 32 + lane16 * 2;
        float4 p0 = pr[0], p1 = pr[1];
        float4 q0 = qr[0], q1 = qr[1];

        float h0 = fmaxf(p0.x + q0.x + b1a.x, 0.f);
        float h1 = fmaxf(p0.y + q0.y + b1a.y, 0.f);
        float h2 = fmaxf(p0.z + q0.z + b1a.z, 0.f);
        float h3 = fmaxf(p0.w + q0.w + b1a.w, 0.f);
        float h4 = fmaxf(p1.x + q1.x + b1b.x, 0.f);
        float h5 = fmaxf(p1.y + q1.y + b1b.y, 0.f);
        float h6 = fmaxf(p1.z + q1.z + b1b.z, 0.f);
        float h7 = fmaxf(p1.w + q1.w + b1b.w, 0.f);

        float p = h0 * w2a.x;
        p = fmaf(h1, w2a.y, p);
        p = fmaf(h2, w2a.z, p);
        p = fmaf(h3, w2a.w, p);
        p = fmaf(h4, w2b.x, p);
        p = fmaf(h5, w2b.y, p);
        p = fmaf(h6, w2b.z, p);
        p = fmaf(h7, w2b.w, p);
        #pragma unroll
        for (int o = 8; o > 0; o >>= 1) p += __shfl_xor_sync(0xFFFFFFFFu, p, o);
        if (lane16 == 0) g_exps[e] = expf(p + b2v);
    }
}

// ---------------- sum + last-block final reduce ----------------
__global__ void k_sumexp(int E) {
    __shared__ float sdata[256];
    __shared__ int   is_last;
    float s = 0.f;
    for (int i = blockIdx.x * 256 + threadIdx.x; i < E; i += RED_BLOCKS * 256)
        s += g_exps[i];
    sdata[threadIdx.x] = s;
    __syncthreads();
    for (int o = 128; o > 0; o >>= 1) {
        if (threadIdx.x < o) sdata[threadIdx.x] += sdata[threadIdx.x + o];
        __syncthreads();
    }
    if (threadIdx.x == 0) {
        g_partials[blockIdx.x] = sdata[0];
        __threadfence();
        int old = atomicAdd(&g_done, 1);
        is_last = (old == RED_BLOCKS - 1) ? 1 : 0;
    }
    __syncthreads();
    if (is_last) {
        float t = 0.f;
        for (int i = threadIdx.x; i < RED_BLOCKS; i += 256) t += g_partials[i];
        sdata[threadIdx.x] = t;
        __syncthreads();
        for (int o = 128; o > 0; o >>= 1) {
            if (threadIdx.x < o) sdata[threadIdx.x] += sdata[threadIdx.x + o];
            __syncthreads();
        }
        if (threadIdx.x == 0) {
            g_inv_total = 1.f / sdata[0];
            g_done = 0;   // reset for next graph replay
        }
    }
}

__global__ void k_norm(float4* __restrict__ out, int n4) {
    int i = blockIdx.x * blockDim.x + threadIdx.x;
    if (i < n4) {
        float inv = g_inv_total;
        float4 v = ((const float4*)g_exps)[i];
        out[i] = make_float4(v.x * inv, v.y * inv, v.z * inv, v.w * inv);
    }
}
__global__ void k_norm_tail(float* __restrict__ out, int start, int E) {
    int i = start + blockIdx.x * blockDim.x + threadIdx.x;
    if (i < E) out[i] = g_exps[i] * g_inv_total;
}

extern "C" void kernel_launch(void* const* d_in, const int* in_sizes, int n_in,
                              void* d_out, int out_size) {
    const float* emb = (const float*)d_in[0];
    const int*   lm  = (const int*)d_in[1];
    const float* W1  = (const float*)d_in[2];
    const float* b1  = (const float*)d_in[3];
    const float* W2  = (const float*)d_in[4];
    const float* b2  = (const float*)d_in[5];
    float* out = (float*)d_out;
    const int E     = in_sizes[1] / 2;
    const int nodes = in_sizes[0] / 128;

    cudaFuncSetAttribute(k_node, cudaFuncAttributeMaxDynamicSharedMemorySize, NODE_SMEM);

    dim3 ngrid((nodes + 127) / 128, 2);
    k_node<<<ngrid, 256, NODE_SMEM>>>(emb, W1, nodes);
    k_edge<<<2048, 256>>>(lm, b1, W2, b2, E);
    k_sumexp<<<RED_BLOCKS, 256>>>(E);
    const int n4 = E >> 2;
    if (n4 > 0) k_norm<<<(n4 + 255) / 256, 256>>>((float4*)out, n4);
    if (E & 3) k_norm_tail<<<1, 256>>>(out, n4 << 2, E);
}

// round 9
// speedup vs baseline: 5.2950x; 1.0865x over previous
#include <cuda_runtime.h>
#include <cuda_fp16.h>
#include <cstdint>

// RelationalPolicyHead, factored + fp32x2 GEMM + fp16 P/Q gathers:
//   P = emb @ U, Q = emb @ V  (U/V = halves of W1)   [k_node, FFMA2, fp16 out]
//   e_exp = exp( W2^T relu(P[src]+Q[tgt]+b1) + b2 )  [k_edge, half-warp/edge, 1 LDG.128/row]
//   total = sum(e_exp) (last-block reduce)           [k_sumexp]
//   probs = e_exp * (1/total)                        [k_norm]

#define RED_BLOCKS 1024
#define MAX_NODES 100000

__device__ __half g_Ph[MAX_NODES * 128];
__device__ __half g_Qh[MAX_NODES * 128];
__device__ float  g_exps[1048576];
__device__ float  g_partials[RED_BLOCKS];
__device__ float  g_inv_total;
__device__ int    g_done = 0;

#define FMA_F32X2(d, a, b, c) \
    asm("fma.rn.f32x2 %0, %1, %2, %3;" : "=l"(d) : "l"(a), "l"(b), "l"(c))
#define DUP_F32X2(d, s) \
    asm("mov.b64 %0, {%1, %1};" : "=l"(d) : "f"(s))
#define UNPACK_F32X2(lo, hi, v) \
    asm("mov.b64 {%0, %1}, %2;" : "=f"(lo), "=f"(hi) : "l"(v))

// ---------------- node GEMM: out = emb @ W1half (FFMA2), fp16 store ----------------
#define NODE_SMEM (2 * 128 * 128 * 4)

__global__ __launch_bounds__(256, 1)
void k_node(const float* __restrict__ emb, const float* __restrict__ W1, int nodes) {
    extern __shared__ float sm[];
    float* As = sm;            // [m][k] 128x128
    float* Bs = sm + 16384;    // [k][n] 128x128

    const int tid = threadIdx.x;
    const int m0 = blockIdx.x * 128;
    const float* Bsrc = W1 + blockIdx.y * 16384;

    {
        const float4* bs4 = (const float4*)Bsrc;
        float4* Bd = (float4*)Bs;
        float4* Ad = (float4*)As;
        #pragma unroll
        for (int t = 0; t < 16; t++) {
            int i4 = t * 256 + tid;
            Bd[i4] = bs4[i4];
            int row = i4 >> 5;
            float4 v = make_float4(0.f, 0.f, 0.f, 0.f);
            if (m0 + row < nodes) v = ((const float4*)emb)[(size_t)(m0 + row) * 32 + (i4 & 31)];
            Ad[i4] = v;
        }
    }
    __syncthreads();

    const int tm8 = (tid >> 4) * 8;
    const int tn8 = (tid & 15) * 8;

    unsigned long long acc2[8][4];
    #pragma unroll
    for (int i = 0; i < 8; i++)
        #pragma unroll
        for (int j = 0; j < 4; j++) acc2[i][j] = 0ull;

    #pragma unroll 2
    for (int k = 0; k < 128; k++) {
        unsigned long long aa[8];
        #pragma unroll
        for (int i = 0; i < 8; i++) {
            float a = As[(tm8 + i) * 128 + k];      // broadcast LDS
            DUP_F32X2(aa[i], a);
        }
        ulonglong2 bv0 = *(const ulonglong2*)(Bs + k * 128 + tn8);      // LDS.128
        ulonglong2 bv1 = *(const ulonglong2*)(Bs + k * 128 + tn8 + 4);  // LDS.128
        unsigned long long bp[4] = {bv0.x, bv0.y, bv1.x, bv1.y};
        #pragma unroll
        for (int i = 0; i < 8; i++)
            #pragma unroll
            for (int j = 0; j < 4; j++)
                FMA_F32X2(acc2[i][j], aa[i], bp[j], acc2[i][j]);
    }

    __half* out = blockIdx.y ? g_Qh : g_Ph;
    #pragma unroll
    for (int i = 0; i < 8; i++) {
        int r = m0 + tm8 + i;
        if (r < nodes) {
            float c[8];
            #pragma unroll
            for (int j = 0; j < 4; j++) UNPACK_F32X2(c[2 * j], c[2 * j + 1], acc2[i][j]);
            __half2 h01 = __floats2half2_rn(c[0], c[1]);
            __half2 h23 = __floats2half2_rn(c[2], c[3]);
            __half2 h45 = __floats2half2_rn(c[4], c[5]);
            __half2 h67 = __floats2half2_rn(c[6], c[7]);
            uint4 pk;
            pk.x = *(uint32_t*)&h01; pk.y = *(uint32_t*)&h23;
            pk.z = *(uint32_t*)&h45; pk.w = *(uint32_t*)&h67;
            *(uint4*)(out + (size_t)r * 128 + tn8) = pk;
        }
    }
}

// ---------------- edge kernel: half-warp per edge, fp16 gathers, fused exp ----------------
__global__ __launch_bounds__(256)
void k_edge(const int* __restrict__ lm, const float* __restrict__ b1,
            const float* __restrict__ W2, const float* __restrict__ b2, int E) {
    const int lane   = threadIdx.x & 31;
    const int lane16 = lane & 15;
    const int hw     = ((blockIdx.x * 256 + threadIdx.x) >> 5) * 2 + (lane >> 4);
    const int nhw    = (gridDim.x * 256) >> 4;

    const float4 b1a = ((const float4*)b1)[lane16 * 2];
    const float4 b1b = ((const float4*)b1)[lane16 * 2 + 1];
    const float4 w2a = ((const float4*)W2)[lane16 * 2];
    const float4 w2b = ((const float4*)W2)[lane16 * 2 + 1];
    const float  b2v = b2[0];

    for (int e = hw; e < E; e += nhw) {
        int s = lm[e];
        int t = lm[E + e];
        uint4 pv = *(const uint4*)(g_Ph + (size_t)s * 128 + lane16 * 8);
        uint4 qv = *(const uint4*)(g_Qh + (size_t)t * 128 + lane16 * 8);

        float2 p0 = __half22float2(*(__half2*)&pv.x);
        float2 p1 = __half22float2(*(__half2*)&pv.y);
        float2 p2 = __half22float2(*(__half2*)&pv.z);
        float2 p3 = __half22float2(*(__half2*)&pv.w);
        float2 q0 = __half22float2(*(__half2*)&qv.x);
        float2 q1 = __half22float2(*(__half2*)&qv.y);
        float2 q2 = __half22float2(*(__half2*)&qv.z);
        float2 q3 = __half22float2(*(__half2*)&qv.w);

        float h0 = fmaxf(p0.x + q0.x + b1a.x, 0.f);
        float h1 = fmaxf(p0.y + q0.y + b1a.y, 0.f);
        float h2 = fmaxf(p1.x + q1.x + b1a.z, 0.f);
        float h3 = fmaxf(p1.y + q1.y + b1a.w, 0.f);
        float h4 = fmaxf(p2.x + q2.x + b1b.x, 0.f);
        float h5 = fmaxf(p2.y + q2.y + b1b.y, 0.f);
        float h6 = fmaxf(p3.x + q3.x + b1b.z, 0.f);
        float h7 = fmaxf(p3.y + q3.y + b1b.w, 0.f);

        float p = h0 * w2a.x;
        p = fmaf(h1, w2a.y, p);
        p = fmaf(h2, w2a.z, p);
        p = fmaf(h3, w2a.w, p);
        p = fmaf(h4, w2b.x, p);
        p = fmaf(h5, w2b.y, p);
        p = fmaf(h6, w2b.z, p);
        p = fmaf(h7, w2b.w, p);
        #pragma unroll
        for (int o = 8; o > 0; o >>= 1) p += __shfl_xor_sync(0xFFFFFFFFu, p, o);
        if (lane16 == 0) g_exps[e] = expf(p + b2v);
    }
}

// ---------------- sum + last-block final reduce ----------------
__global__ void k_sumexp(int E) {
    __shared__ float sdata[256];
    __shared__ int   is_last;
    float s = 0.f;
    for (int i = blockIdx.x * 256 + threadIdx.x; i < E; i += RED_BLOCKS * 256)
        s += g_exps[i];
    sdata[threadIdx.x] = s;
    __syncthreads();
    for (int o = 128; o > 0; o >>= 1) {
        if (threadIdx.x < o) sdata[threadIdx.x] += sdata[threadIdx.x + o];
        __syncthreads();
    }
    if (threadIdx.x == 0) {
        g_partials[blockIdx.x] = sdata[0];
        __threadfence();
        int old = atomicAdd(&g_done, 1);
        is_last = (old == RED_BLOCKS - 1) ? 1 : 0;
    }
    __syncthreads();
    if (is_last) {
        float t = 0.f;
        for (int i = threadIdx.x; i < RED_BLOCKS; i += 256) t += g_partials[i];
        sdata[threadIdx.x] = t;
        __syncthreads();
        for (int o = 128; o > 0; o >>= 1) {
            if (threadIdx.x < o) sdata[threadIdx.x] += sdata[threadIdx.x + o];
            __syncthreads();
        }
        if (threadIdx.x == 0) {
            g_inv_total = 1.f / sdata[0];
            g_done = 0;   // reset for next graph replay
        }
    }
}

__global__ void k_norm(float4* __restrict__ out, int n4) {
    int i = blockIdx.x * blockDim.x + threadIdx.x;
    if (i < n4) {
        float inv = g_inv_total;
        float4 v = ((const float4*)g_exps)[i];
        out[i] = make_float4(v.x * inv, v.y * inv, v.z * inv, v.w * inv);
    }
}
__global__ void k_norm_tail(float* __restrict__ out, int start, int E) {
    int i = start + blockIdx.x * blockDim.x + threadIdx.x;
    if (i < E) out[i] = g_exps[i] * g_inv_total;
}

extern "C" void kernel_launch(void* const* d_in, const int* in_sizes, int n_in,
                              void* d_out, int out_size) {
    const float* emb = (const float*)d_in[0];
    const int*   lm  = (const int*)d_in[1];
    const float* W1  = (const float*)d_in[2];
    const float* b1  = (const float*)d_in[3];
    const float* W2  = (const float*)d_in[4];
    const float* b2  = (const float*)d_in[5];
    float* out = (float*)d_out;
    const int E     = in_sizes[1] / 2;
    const int nodes = in_sizes[0] / 128;

    cudaFuncSetAttribute(k_node, cudaFuncAttributeMaxDynamicSharedMemorySize, NODE_SMEM);

    dim3 ngrid((nodes + 127) / 128, 2);
    k_node<<<ngrid, 256, NODE_SMEM>>>(emb, W1, nodes);
    k_edge<<<2048, 256>>>(lm, b1, W2, b2, E);
    k_sumexp<<<RED_BLOCKS, 256>>>(E);
    const int n4 = E >> 2;
    if (n4 > 0) k_norm<<<(n4 + 255) / 256, 256>>>((float4*)out, n4);
    if (E & 3) k_norm_tail<<<1, 256>>>(out, n4 << 2, E);
}

// round 11
// speedup vs baseline: 8.4986x; 1.6050x over previous
#include <cuda_runtime.h>
#include <cuda_fp16.h>
#include <cstdint>

// RelationalPolicyHead, factored:
//   P = emb @ U, Q = emb @ V  (U/V = halves of W1)   [k_node: mma.sync fp16 HMMA, fp16 out]
//   e_exp = exp( W2^T relu(P[src]+Q[tgt]+b1) + b2 )  [k_edge: half-warp/edge + fused sum-reduce]
//   probs = e_exp * (1/total)                        [k_norm]

#define EDGE_BLOCKS 2048
#define MAX_NODES 100000
#define NSTR 136   // half-elements per smem row (272 B): conflict-free ldmatrix + B loads

__device__ __half g_Ph[MAX_NODES * 128];
__device__ __half g_Qh[MAX_NODES * 128];
__device__ float  g_exps[1048576];
__device__ float  g_partials[EDGE_BLOCKS];
__device__ float  g_inv_total;
__device__ int    g_done = 0;

__device__ __forceinline__ uint32_t smem_u32(const void* p) {
    uint32_t a;
    asm("{ .reg .u64 t; cvta.to.shared.u64 t, %1; cvt.u32.u64 %0, t; }" : "=r"(a) : "l"(p));
    return a;
}

// ---------------- node GEMM via mma.sync m16n8k16 fp16 ----------------
// tile M=128 nodes x N=128, K=128. 8 warps; warp w owns rows w*16..w*16+15.
#define NODE_SMEM (2 * 128 * NSTR * 2)   // As + Bs, fp16

__global__ __launch_bounds__(256, 1)
void k_node(const float* __restrict__ emb, const float* __restrict__ W1, int nodes) {
    extern __shared__ __half hsm[];
    __half* As = hsm;                 // [m][k]  128 x NSTR
    __half* Bs = hsm + 128 * NSTR;    // [n][k]  128 x NSTR  (W1half transposed)

    const int tid  = threadIdx.x;
    const int lane = tid & 31;
    const int w    = tid >> 5;
    const int m0   = blockIdx.x * 128;
    const float* Wsrc = W1 + blockIdx.y * 16384;

    // A: 128x128 floats -> fp16, guarded rows
    {
        #pragma unroll
        for (int t = 0; t < 16; t++) {
            int i4 = t * 256 + tid;           // float4 index
            int row = i4 >> 5, c4 = (i4 & 31) * 4;
            float4 v = make_float4(0.f, 0.f, 0.f, 0.f);
            if (m0 + row < nodes) v = ((const float4*)emb)[(size_t)(m0 + row) * 32 + (i4 & 31)];
            __half2 h01 = __floats2half2_rn(v.x, v.y);
            __half2 h23 = __floats2half2_rn(v.z, v.w);
            uint32_t* dst = (uint32_t*)(As + row * NSTR + c4);
            dst[0] = *(uint32_t*)&h01;
            dst[1] = *(uint32_t*)&h23;
        }
    }
    // B: W[k][n] -> Bs[n][k] fp16 (transpose)
    for (int idx = tid; idx < 16384; idx += 256) {
        int k = idx >> 7, n = idx & 127;
        Bs[n * NSTR + k] = __float2half_rn(Wsrc[idx]);
    }
    __syncthreads();

    const uint32_t as_base = smem_u32(As);

    float acc[16][4];
    #pragma unroll
    for (int i = 0; i < 16; i++)
        #pragma unroll
        for (int j = 0; j < 4; j++) acc[i][j] = 0.f;

    const int bn  = lane >> 2;          // 0..7
    const int bk0 = (lane & 3) * 2;     // 0,2,4,6

    #pragma unroll
    for (int kc = 0; kc < 8; kc++) {
        // A fragment via ldmatrix.x4
        int lrow = w * 16 + (lane & 7) + ((lane >> 3) & 1) * 8;
        int lcol = kc * 16 + (lane >> 4) * 8;
        uint32_t aaddr = as_base + (uint32_t)(lrow * NSTR + lcol) * 2u;
        uint32_t a0, a1, a2, a3;
        asm volatile("ldmatrix.sync.aligned.m8n8.x4.shared.b16 {%0,%1,%2,%3}, [%4];"
                     : "=r"(a0), "=r"(a1), "=r"(a2), "=r"(a3) : "r"(aaddr));

        const __half* bcol = Bs + kc * 16 + bk0;
        #pragma unroll
        for (int n8 = 0; n8 < 16; n8++) {
            const __half* bp = bcol + (n8 * 8 + bn) * NSTR;
            uint32_t b0 = *(const uint32_t*)bp;
            uint32_t b1 = *(const uint32_t*)(bp + 8);
            asm volatile(
                "mma.sync.aligned.m16n8k16.row.col.f32.f16.f16.f32 "
                "{%0,%1,%2,%3}, {%4,%5,%6,%7}, {%8,%9}, {%0,%1,%2,%3};"
                : "+f"(acc[n8][0]), "+f"(acc[n8][1]), "+f"(acc[n8][2]), "+f"(acc[n8][3])
                : "r"(a0), "r"(a1), "r"(a2), "r"(a3), "r"(b0), "r"(b1));
        }
    }

    // epilogue: fp16 store. c0,c1 -> (r0, cb..cb+1); c2,c3 -> (r0+8, ...)
    __half* out = blockIdx.y ? g_Qh : g_Ph;
    const int r0 = m0 + w * 16 + (lane >> 2);
    const int cb = (lane & 3) * 2;
    if (r0 < nodes) {
        #pragma unroll
        for (int n8 = 0; n8 < 16; n8++) {
            __half2 h = __floats2half2_rn(acc[n8][0], acc[n8][1]);
            *(uint32_t*)(out + (size_t)r0 * 128 + n8 * 8 + cb) = *(uint32_t*)&h;
        }
    }
    if (r0 + 8 < nodes) {
        #pragma unroll
        for (int n8 = 0; n8 < 16; n8++) {
            __half2 h = __floats2half2_rn(acc[n8][2], acc[n8][3]);
            *(uint32_t*)(out + (size_t)(r0 + 8) * 128 + n8 * 8 + cb) = *(uint32_t*)&h;
        }
    }
}

// ---------------- edge kernel: half-warp/edge, fp16 gathers, fused exp + sum ----------------
__global__ __launch_bounds__(256)
void k_edge(const int* __restrict__ lm, const float* __restrict__ b1,
            const float* __restrict__ W2, const float* __restrict__ b2, int E) {
    __shared__ float sdata[256];
    __shared__ int   is_last;
    const int lane   = threadIdx.x & 31;
    const int lane16 = lane & 15;
    const int hw     = ((blockIdx.x * 256 + threadIdx.x) >> 5) * 2 + (lane >> 4);
    const int nhw    = (EDGE_BLOCKS * 256) >> 4;

    const float4 b1a = ((const float4*)b1)[lane16 * 2];
    const float4 b1b = ((const float4*)b1)[lane16 * 2 + 1];
    const float4 w2a = ((const float4*)W2)[lane16 * 2];
    const float4 w2b = ((const float4*)W2)[lane16 * 2 + 1];
    const float  b2v = b2[0];

    float s = 0.f;
    for (int e = hw; e < E; e += nhw) {
        int sn = lm[e];
        int tn = lm[E + e];
        uint4 pv = *(const uint4*)(g_Ph + (size_t)sn * 128 + lane16 * 8);
        uint4 qv = *(const uint4*)(g_Qh + (size_t)tn * 128 + lane16 * 8);

        float2 p0 = __half22float2(*(__half2*)&pv.x);
        float2 p1 = __half22float2(*(__half2*)&pv.y);
        float2 p2 = __half22float2(*(__half2*)&pv.z);
        float2 p3 = __half22float2(*(__half2*)&pv.w);
        float2 q0 = __half22float2(*(__half2*)&qv.x);
        float2 q1 = __half22float2(*(__half2*)&qv.y);
        float2 q2 = __half22float2(*(__half2*)&qv.z);
        float2 q3 = __half22float2(*(__half2*)&qv.w);

        float h0 = fmaxf(p0.x + q0.x + b1a.x, 0.f);
        float h1 = fmaxf(p0.y + q0.y + b1a.y, 0.f);
        float h2 = fmaxf(p1.x + q1.x + b1a.z, 0.f);
        float h3 = fmaxf(p1.y + q1.y + b1a.w, 0.f);
        float h4 = fmaxf(p2.x + q2.x + b1b.x, 0.f);
        float h5 = fmaxf(p2.y + q2.y + b1b.y, 0.f);
        float h6 = fmaxf(p3.x + q3.x + b1b.z, 0.f);
        float h7 = fmaxf(p3.y + q3.y + b1b.w, 0.f);

        float p = h0 * w2a.x;
        p = fmaf(h1, w2a.y, p);
        p = fmaf(h2, w2a.z, p);
        p = fmaf(h3, w2a.w, p);
        p = fmaf(h4, w2b.x, p);
        p = fmaf(h5, w2b.y, p);
        p = fmaf(h6, w2b.z, p);
        p = fmaf(h7, w2b.w, p);
        #pragma unroll
        for (int o = 8; o > 0; o >>= 1) p += __shfl_xor_sync(0xFFFFFFFFu, p, o);
        if (lane16 == 0) {
            float ex = expf(p + b2v);
            g_exps[e] = ex;
            s += ex;
        }
    }

    // block reduce + last-block finish
    sdata[threadIdx.x] = s;
    __syncthreads();
    for (int o = 128; o > 0; o >>= 1) {
        if (threadIdx.x < o) sdata[threadIdx.x] += sdata[threadIdx.x + o];
        __syncthreads();
    }
    if (threadIdx.x == 0) {
        g_partials[blockIdx.x] = sdata[0];
        __threadfence();
        int old = atomicAdd(&g_done, 1);
        is_last = (old == EDGE_BLOCKS - 1) ? 1 : 0;
    }
    __syncthreads();
    if (is_last) {
        float t = 0.f;
        for (int i = threadIdx.x; i < EDGE_BLOCKS; i += 256) t += g_partials[i];
        sdata[threadIdx.x] = t;
        __syncthreads();
        for (int o = 128; o > 0; o >>= 1) {
            if (threadIdx.x < o) sdata[threadIdx.x] += sdata[threadIdx.x + o];
            __syncthreads();
        }
        if (threadIdx.x == 0) {
            g_inv_total = 1.f / sdata[0];
            g_done = 0;   // reset for graph replay
        }
    }
}

__global__ void k_norm(float4* __restrict__ out, int n4) {
    int i = blockIdx.x * blockDim.x + threadIdx.x;
    if (i < n4) {
        float inv = g_inv_total;
        float4 v = ((const float4*)g_exps)[i];
        out[i] = make_float4(v.x * inv, v.y * inv, v.z * inv, v.w * inv);
    }
}
__global__ void k_norm_tail(float* __restrict__ out, int start, int E) {
    int i = start + blockIdx.x * blockDim.x + threadIdx.x;
    if (i < E) out[i] = g_exps[i] * g_inv_total;
}

extern "C" void kernel_launch(void* const* d_in, const int* in_sizes, int n_in,
                              void* d_out, int out_size) {
    const float* emb = (const float*)d_in[0];
    const int*   lm  = (const int*)d_in[1];
    const float* W1  = (const float*)d_in[2];
    const float* b1  = (const float*)d_in[3];
    const float* W2  = (const float*)d_in[4];
    const float* b2  = (const float*)d_in[5];
    float* out = (float*)d_out;
    const int E     = in_sizes[1] / 2;
    const int nodes = in_sizes[0] / 128;

    cudaFuncSetAttribute(k_node, cudaFuncAttributeMaxDynamicSharedMemorySize, NODE_SMEM);

    dim3 ngrid((nodes + 127) / 128, 2);
    k_node<<<ngrid, 256, NODE_SMEM>>>(emb, W1, nodes);
    k_edge<<<EDGE_BLOCKS, 256>>>(lm, b1, W2, b2, E);
    const int n4 = E >> 2;
    if (n4 > 0) k_norm<<<(n4 + 255) / 256, 256>>>((float4*)out, n4);
    if (E & 3) k_norm_tail<<<1, 256>>>(out, n4 << 2, E);
}

// round 12
// speedup vs baseline: 11.1866x; 1.3163x over previous
#include <cuda_runtime.h>
#include <cuda_fp16.h>
#include <cstdint>

// RelationalPolicyHead, factored:
//   W1T fp16 pre-transposed once                      [k_prep]
//   P = emb @ U, Q = emb @ V                          [k_node: persistent HMMA, ldmatrix A+B]
//   e_exp = exp( W2^T relu(P[src]+Q[tgt]+b1) + b2 )   [k_edge: half-warp/edge + fused sum]
//   probs = e_exp * (1/total)                         [k_norm]

#define EDGE_BLOCKS 2048
#define MAX_NODES 100000
#define NSTR 136   // halves per smem row (272 B = 68 words): conflict-free ldmatrix

__device__ __half g_Wt[2 * 128 * 128];   // [half][n][k] fp16
__device__ __half g_Ph[MAX_NODES * 128];
__device__ __half g_Qh[MAX_NODES * 128];
__device__ float  g_exps[1048576];
__device__ float  g_partials[EDGE_BLOCKS];
__device__ float  g_inv_total;
__device__ int    g_done = 0;

__device__ __forceinline__ uint32_t smem_u32(const void* p) {
    uint32_t a;
    asm("{ .reg .u64 t; cvta.to.shared.u64 t, %1; cvt.u32.u64 %0, t; }" : "=r"(a) : "l"(p));
    return a;
}

// ---------------- W1 -> fp16 transposed [h][n][k] ----------------
__global__ void k_prep(const float* __restrict__ W1) {
    int i = blockIdx.x * 256 + threadIdx.x;          // 32768
    int h = i >> 14, r = i & 16383;
    int n = r >> 7, k = r & 127;
    g_Wt[i] = __float2half_rn(W1[h * 16384 + k * 128 + n]);
}

// ---------------- node GEMM: persistent, mma.sync m16n8k16 ----------------
#define NODE_SMEM (2 * 128 * NSTR * 2)   // As + Bs fp16

__global__ __launch_bounds__(256, 2)
void k_node(const float* __restrict__ emb, int nodes, int ntiles) {
    extern __shared__ __half hsm[];
    __half* As = hsm;                 // [m][k] 128 x NSTR
    __half* Bs = hsm + 128 * NSTR;    // [n][k] 128 x NSTR

    const int tid  = threadIdx.x;
    const int lane = tid & 31;
    const int w    = tid >> 5;
    const int by   = blockIdx.x & 1;          // 0 -> U/P, 1 -> V/Q
    const int t0   = blockIdx.x >> 1;         // starting m-tile

    // ---- load B half once (pre-transposed fp16, vectorized) ----
    {
        const uint4* src = (const uint4*)(g_Wt + by * 16384);
        #pragma unroll
        for (int it = 0; it < 8; it++) {
            int i = it * 256 + tid;            // uint4 index: 128 rows x 16
            int r = i >> 4, c8 = (i & 15) * 8;
            *(uint4*)(Bs + r * NSTR + c8) = src[i];
        }
    }

    const uint32_t as_base = smem_u32(As);
    const uint32_t bs_base = smem_u32(Bs);

    // B-ldmatrix per-thread row base (halves): mat = lane>>3 selects {n-lo/k-lo, n-lo/k-hi, n-hi/k-lo, n-hi/k-hi}
    const int bmat = lane >> 3, bs_ = lane & 7;
    const uint32_t brow_off = (uint32_t)((((bmat >> 1) * 8 + bs_) * NSTR + (bmat & 1) * 8) * 2);

    // A-ldmatrix per-thread row
    const int arow = (lane & 7) + ((lane >> 3) & 1) * 8;
    const int acol8 = (lane >> 4) * 8;

    __half* out = by ? g_Qh : g_Ph;

    for (int t = t0; t < ntiles; t += 148) {
        const int m0 = t * 128;

        __syncthreads();   // previous iteration's consumers done before A overwrite
        #pragma unroll
        for (int it = 0; it < 16; it++) {
            int i4 = it * 256 + tid;
            int row = i4 >> 5, c4 = (i4 & 31) * 4;
            float4 v = make_float4(0.f, 0.f, 0.f, 0.f);
            if (m0 + row < nodes) v = ((const float4*)emb)[(size_t)(m0 + row) * 32 + (i4 & 31)];
            __half2 h01 = __floats2half2_rn(v.x, v.y);
            __half2 h23 = __floats2half2_rn(v.z, v.w);
            uint2 pk;
            pk.x = *(uint32_t*)&h01; pk.y = *(uint32_t*)&h23;
            *(uint2*)(As + row * NSTR + c4) = pk;
        }
        __syncthreads();

        float acc[16][4];
        #pragma unroll
        for (int i = 0; i < 16; i++)
            #pragma unroll
            for (int j = 0; j < 4; j++) acc[i][j] = 0.f;

        #pragma unroll
        for (int kc = 0; kc < 8; kc++) {
            uint32_t a0, a1, a2, a3;
            uint32_t aaddr = as_base + (uint32_t)(((w * 16 + arow) * NSTR) + kc * 16 + acol8) * 2u;
            asm volatile("ldmatrix.sync.aligned.m8n8.x4.shared.b16 {%0,%1,%2,%3}, [%4];"
                         : "=r"(a0), "=r"(a1), "=r"(a2), "=r"(a3) : "r"(aaddr));

            #pragma unroll
            for (int g = 0; g < 8; g++) {
                uint32_t baddr = bs_base + brow_off
                               + (uint32_t)(g * 16 * NSTR + kc * 16) * 2u;
                uint32_t b0, b1, b2, b3;
                asm volatile("ldmatrix.sync.aligned.m8n8.x4.shared.b16 {%0,%1,%2,%3}, [%4];"
                             : "=r"(b0), "=r"(b1), "=r"(b2), "=r"(b3) : "r"(baddr));
                asm volatile(
                    "mma.sync.aligned.m16n8k16.row.col.f32.f16.f16.f32 "
                    "{%0,%1,%2,%3}, {%4,%5,%6,%7}, {%8,%9}, {%0,%1,%2,%3};"
                    : "+f"(acc[2*g][0]), "+f"(acc[2*g][1]), "+f"(acc[2*g][2]), "+f"(acc[2*g][3])
                    : "r"(a0), "r"(a1), "r"(a2), "r"(a3), "r"(b0), "r"(b1));
                asm volatile(
                    "mma.sync.aligned.m16n8k16.row.col.f32.f16.f16.f32 "
                    "{%0,%1,%2,%3}, {%4,%5,%6,%7}, {%8,%9}, {%0,%1,%2,%3};"
                    : "+f"(acc[2*g+1][0]), "+f"(acc[2*g+1][1]), "+f"(acc[2*g+1][2]), "+f"(acc[2*g+1][3])
                    : "r"(a0), "r"(a1), "r"(a2), "r"(a3), "r"(b2), "r"(b3));
            }
        }

        const int r0 = m0 + w * 16 + (lane >> 2);
        const int cb = (lane & 3) * 2;
        if (r0 < nodes) {
            #pragma unroll
            for (int n8 = 0; n8 < 16; n8++) {
                __half2 h = __floats2half2_rn(acc[n8][0], acc[n8][1]);
                *(uint32_t*)(out + (size_t)r0 * 128 + n8 * 8 + cb) = *(uint32_t*)&h;
            }
        }
        if (r0 + 8 < nodes) {
            #pragma unroll
            for (int n8 = 0; n8 < 16; n8++) {
                __half2 h = __floats2half2_rn(acc[n8][2], acc[n8][3]);
                *(uint32_t*)(out + (size_t)(r0 + 8) * 128 + n8 * 8 + cb) = *(uint32_t*)&h;
            }
        }
    }
}

// ---------------- edge kernel: half-warp/edge, fp16 gathers, fused exp + sum ----------------
__global__ __launch_bounds__(256)
void k_edge(const int* __restrict__ lm, const float* __restrict__ b1,
            const float* __restrict__ W2, const float* __restrict__ b2, int E) {
    __shared__ float sdata[256];
    __shared__ int   is_last;
    const int lane   = threadIdx.x & 31;
    const int lane16 = lane & 15;
    const int hw     = ((blockIdx.x * 256 + threadIdx.x) >> 5) * 2 + (lane >> 4);
    const int nhw    = (EDGE_BLOCKS * 256) >> 4;

    const float4 b1a = ((const float4*)b1)[lane16 * 2];
    const float4 b1b = ((const float4*)b1)[lane16 * 2 + 1];
    const float4 w2a = ((const float4*)W2)[lane16 * 2];
    const float4 w2b = ((const float4*)W2)[lane16 * 2 + 1];
    const float  b2v = b2[0];

    float s = 0.f;
    for (int e = hw; e < E; e += nhw) {
        int sn = lm[e];
        int tn = lm[E + e];
        uint4 pv = *(const uint4*)(g_Ph + (size_t)sn * 128 + lane16 * 8);
        uint4 qv = *(const uint4*)(g_Qh + (size_t)tn * 128 + lane16 * 8);

        float2 p0 = __half22float2(*(__half2*)&pv.x);
        float2 p1 = __half22float2(*(__half2*)&pv.y);
        float2 p2 = __half22float2(*(__half2*)&pv.z);
        float2 p3 = __half22float2(*(__half2*)&pv.w);
        float2 q0 = __half22float2(*(__half2*)&qv.x);
        float2 q1 = __half22float2(*(__half2*)&qv.y);
        float2 q2 = __half22float2(*(__half2*)&qv.z);
        float2 q3 = __half22float2(*(__half2*)&qv.w);

        float h0 = fmaxf(p0.x + q0.x + b1a.x, 0.f);
        float h1 = fmaxf(p0.y + q0.y + b1a.y, 0.f);
        float h2 = fmaxf(p1.x + q1.x + b1a.z, 0.f);
        float h3 = fmaxf(p1.y + q1.y + b1a.w, 0.f);
        float h4 = fmaxf(p2.x + q2.x + b1b.x, 0.f);
        float h5 = fmaxf(p2.y + q2.y + b1b.y, 0.f);
        float h6 = fmaxf(p3.x + q3.x + b1b.z, 0.f);
        float h7 = fmaxf(p3.y + q3.y + b1b.w, 0.f);

        float p = h0 * w2a.x;
        p = fmaf(h1, w2a.y, p);
        p = fmaf(h2, w2a.z, p);
        p = fmaf(h3, w2a.w, p);
        p = fmaf(h4, w2b.x, p);
        p = fmaf(h5, w2b.y, p);
        p = fmaf(h6, w2b.z, p);
        p = fmaf(h7, w2b.w, p);
        #pragma unroll
        for (int o = 8; o > 0; o >>= 1) p += __shfl_xor_sync(0xFFFFFFFFu, p, o);
        if (lane16 == 0) {
            float ex = expf(p + b2v);
            g_exps[e] = ex;
            s += ex;
        }
    }

    sdata[threadIdx.x] = s;
    __syncthreads();
    for (int o = 128; o > 0; o >>= 1) {
        if (threadIdx.x < o) sdata[threadIdx.x] += sdata[threadIdx.x + o];
        __syncthreads();
    }
    if (threadIdx.x == 0) {
        g_partials[blockIdx.x] = sdata[0];
        __threadfence();
        int old = atomicAdd(&g_done, 1);
        is_last = (old == EDGE_BLOCKS - 1) ? 1 : 0;
    }
    __syncthreads();
    if (is_last) {
        float t = 0.f;
        for (int i = threadIdx.x; i < EDGE_BLOCKS; i += 256) t += g_partials[i];
        sdata[threadIdx.x] = t;
        __syncthreads();
        for (int o = 128; o > 0; o >>= 1) {
            if (threadIdx.x < o) sdata[threadIdx.x] += sdata[threadIdx.x + o];
            __syncthreads();
        }
        if (threadIdx.x == 0) {
            g_inv_total = 1.f / sdata[0];
            g_done = 0;   // reset for graph replay
        }
    }
}

__global__ void k_norm(float4* __restrict__ out, int n4) {
    int i = blockIdx.x * blockDim.x + threadIdx.x;
    if (i < n4) {
        float inv = g_inv_total;
        float4 v = ((const float4*)g_exps)[i];
        out[i] = make_float4(v.x * inv, v.y * inv, v.z * inv, v.w * inv);
    }
}
__global__ void k_norm_tail(float* __restrict__ out, int start, int E) {
    int i = start + blockIdx.x * blockDim.x + threadIdx.x;
    if (i < E) out[i] = g_exps[i] * g_inv_total;
}

extern "C" void kernel_launch(void* const* d_in, const int* in_sizes, int n_in,
                              void* d_out, int out_size) {
    const float* emb = (const float*)d_in[0];
    const int*   lm  = (const int*)d_in[1];
    const float* W1  = (const float*)d_in[2];
    const float* b1  = (const float*)d_in[3];
    const float* W2  = (const float*)d_in[4];
    const float* b2  = (const float*)d_in[5];
    float* out = (float*)d_out;
    const int E      = in_sizes[1] / 2;
    const int nodes  = in_sizes[0] / 128;
    const int ntiles = (nodes + 127) / 128;

    cudaFuncSetAttribute(k_node, cudaFuncAttributeMaxDynamicSharedMemorySize, NODE_SMEM);

    k_prep<<<128, 256>>>(W1);
    k_node<<<296, 256, NODE_SMEM>>>(emb, nodes, ntiles);
    k_edge<<<EDGE_BLOCKS, 256>>>(lm, b1, W2, b2, E);
    const int n4 = E >> 2;
    if (n4 > 0) k_norm<<<(n4 + 255) / 256, 256>>>((float4*)out, n4);
    if (E & 3) k_norm_tail<<<1, 256>>>(out, n4 << 2, E);
}

// round 13
// speedup vs baseline: 13.8024x; 1.2338x over previous
#include <cuda_runtime.h>
#include <cuda_fp16.h>
#include <cstdint>

// RelationalPolicyHead, factored:
//   W1T fp16 pre-transposed once                      [k_prep]
//   P = emb @ U, Q = emb @ V + b1                     [k_node: persistent HMMA, ldmatrix A+B]
//   e_exp = exp( W2^T relu(P[src]+Q'[tgt]) + b2 )     [k_edge: half-warp/edge, half2 math, fused sum]
//   probs = e_exp * (1/total)                         [k_norm]

#define EDGE_BLOCKS 2048
#define MAX_NODES 100000
#define NSTR 136   // halves per smem row (272 B): conflict-free ldmatrix

__device__ __half g_Wt[2 * 128 * 128];   // [half][n][k] fp16
__device__ __half g_Ph[MAX_NODES * 128];
__device__ __half g_Qh[MAX_NODES * 128];
__device__ float  g_exps[1048576];
__device__ float  g_partials[EDGE_BLOCKS];
__device__ float  g_inv_total;
__device__ int    g_done = 0;

__device__ __forceinline__ uint32_t smem_u32(const void* p) {
    uint32_t a;
    asm("{ .reg .u64 t; cvta.to.shared.u64 t, %1; cvt.u32.u64 %0, t; }" : "=r"(a) : "l"(p));
    return a;
}

// ---------------- W1 -> fp16 transposed [h][n][k] ----------------
__global__ void k_prep(const float* __restrict__ W1) {
    int i = blockIdx.x * 256 + threadIdx.x;          // 32768
    int h = i >> 14, r = i & 16383;
    int n = r >> 7, k = r & 127;
    g_Wt[i] = __float2half_rn(W1[h * 16384 + k * 128 + n]);
}

// ---------------- node GEMM: persistent, mma.sync m16n8k16 ----------------
#define NODE_SMEM (2 * 128 * NSTR * 2 + 512)   // As + Bs fp16 + b1f

__global__ __launch_bounds__(256, 2)
void k_node(const float* __restrict__ emb, const float* __restrict__ b1,
            int nodes, int ntiles) {
    extern __shared__ __half hsm[];
    __half* As = hsm;                 // [m][k] 128 x NSTR
    __half* Bs = hsm + 128 * NSTR;    // [n][k] 128 x NSTR
    float*  b1f = (float*)(hsm + 2 * 128 * NSTR);

    const int tid  = threadIdx.x;
    const int lane = tid & 31;
    const int w    = tid >> 5;
    const int by   = blockIdx.x & 1;          // 0 -> U/P, 1 -> V/Q(+b1)
    const int t0   = blockIdx.x >> 1;

    // ---- load B half once; b1 into smem (folded into Q only) ----
    {
        const uint4* src = (const uint4*)(g_Wt + by * 16384);
        #pragma unroll
        for (int it = 0; it < 8; it++) {
            int i = it * 256 + tid;
            int r = i >> 4, c8 = (i & 15) * 8;
            *(uint4*)(Bs + r * NSTR + c8) = src[i];
        }
        if (tid < 128) b1f[tid] = by ? b1[tid] : 0.f;
    }

    const uint32_t as_base = smem_u32(As);
    const uint32_t bs_base = smem_u32(Bs);

    const int bmat = lane >> 3, bs_ = lane & 7;
    const uint32_t brow_off = (uint32_t)((((bmat >> 1) * 8 + bs_) * NSTR + (bmat & 1) * 8) * 2);
    const int arow = (lane & 7) + ((lane >> 3) & 1) * 8;
    const int acol8 = (lane >> 4) * 8;

    __half* out = by ? g_Qh : g_Ph;

    for (int t = t0; t < ntiles; t += 148) {
        const int m0 = t * 128;

        __syncthreads();
        #pragma unroll
        for (int it = 0; it < 16; it++) {
            int i4 = it * 256 + tid;
            int row = i4 >> 5, c4 = (i4 & 31) * 4;
            float4 v = make_float4(0.f, 0.f, 0.f, 0.f);
            if (m0 + row < nodes) v = ((const float4*)emb)[(size_t)(m0 + row) * 32 + (i4 & 31)];
            __half2 h01 = __floats2half2_rn(v.x, v.y);
            __half2 h23 = __floats2half2_rn(v.z, v.w);
            uint2 pk;
            pk.x = *(uint32_t*)&h01; pk.y = *(uint32_t*)&h23;
            *(uint2*)(As + row * NSTR + c4) = pk;
        }
        __syncthreads();

        float acc[16][4];
        #pragma unroll
        for (int i = 0; i < 16; i++)
            #pragma unroll
            for (int j = 0; j < 4; j++) acc[i][j] = 0.f;

        #pragma unroll
        for (int kc = 0; kc < 8; kc++) {
            uint32_t a0, a1, a2, a3;
            uint32_t aaddr = as_base + (uint32_t)(((w * 16 + arow) * NSTR) + kc * 16 + acol8) * 2u;
            asm volatile("ldmatrix.sync.aligned.m8n8.x4.shared.b16 {%0,%1,%2,%3}, [%4];"
                         : "=r"(a0), "=r"(a1), "=r"(a2), "=r"(a3) : "r"(aaddr));

            #pragma unroll
            for (int g = 0; g < 8; g++) {
                uint32_t baddr = bs_base + brow_off
                               + (uint32_t)(g * 16 * NSTR + kc * 16) * 2u;
                uint32_t b0, b1r, b2, b3;
                asm volatile("ldmatrix.sync.aligned.m8n8.x4.shared.b16 {%0,%1,%2,%3}, [%4];"
                             : "=r"(b0), "=r"(b1r), "=r"(b2), "=r"(b3) : "r"(baddr));
                asm volatile(
                    "mma.sync.aligned.m16n8k16.row.col.f32.f16.f16.f32 "
                    "{%0,%1,%2,%3}, {%4,%5,%6,%7}, {%8,%9}, {%0,%1,%2,%3};"
                    : "+f"(acc[2*g][0]), "+f"(acc[2*g][1]), "+f"(acc[2*g][2]), "+f"(acc[2*g][3])
                    : "r"(a0), "r"(a1), "r"(a2), "r"(a3), "r"(b0), "r"(b1r));
                asm volatile(
                    "mma.sync.aligned.m16n8k16.row.col.f32.f16.f16.f32 "
                    "{%0,%1,%2,%3}, {%4,%5,%6,%7}, {%8,%9}, {%0,%1,%2,%3};"
                    : "+f"(acc[2*g+1][0]), "+f"(acc[2*g+1][1]), "+f"(acc[2*g+1][2]), "+f"(acc[2*g+1][3])
                    : "r"(a0), "r"(a1), "r"(a2), "r"(a3), "r"(b2), "r"(b3));
            }
        }

        const int r0 = m0 + w * 16 + (lane >> 2);
        const int cb = (lane & 3) * 2;
        if (r0 < nodes) {
            #pragma unroll
            for (int n8 = 0; n8 < 16; n8++) {
                float bx = b1f[n8 * 8 + cb], by2 = b1f[n8 * 8 + cb + 1];
                __half2 h = __floats2half2_rn(acc[n8][0] + bx, acc[n8][1] + by2);
                *(uint32_t*)(out + (size_t)r0 * 128 + n8 * 8 + cb) = *(uint32_t*)&h;
            }
        }
        if (r0 + 8 < nodes) {
            #pragma unroll
            for (int n8 = 0; n8 < 16; n8++) {
                float bx = b1f[n8 * 8 + cb], by2 = b1f[n8 * 8 + cb + 1];
                __half2 h = __floats2half2_rn(acc[n8][2] + bx, acc[n8][3] + by2);
                *(uint32_t*)(out + (size_t)(r0 + 8) * 128 + n8 * 8 + cb) = *(uint32_t*)&h;
            }
        }
    }
}

// ---------------- edge kernel: half-warp/edge, half2 math, fused exp + sum ----------------
__global__ __launch_bounds__(256)
void k_edge(const int* __restrict__ lm, const float* __restrict__ W2,
            const float* __restrict__ b2, int E) {
    __shared__ float sdata[256];
    __shared__ int   is_last;
    const int lane   = threadIdx.x & 31;
    const int lane16 = lane & 15;
    const int hw     = ((blockIdx.x * 256 + threadIdx.x) >> 5) * 2 + (lane >> 4);
    const int nhw    = (EDGE_BLOCKS * 256) >> 4;

    const float4 w2a = ((const float4*)W2)[lane16 * 2];
    const float4 w2b = ((const float4*)W2)[lane16 * 2 + 1];
    const float  b2v = b2[0];
    const __half2 z  = __float2half2_rn(0.f);

    float s = 0.f;
    for (int e = hw; e < E; e += nhw) {
        int sn = lm[e];
        int tn = lm[E + e];
        uint4 pv = *(const uint4*)(g_Ph + (size_t)sn * 128 + lane16 * 8);
        uint4 qv = *(const uint4*)(g_Qh + (size_t)tn * 128 + lane16 * 8);

        __half2 s0 = __hmax2(__hadd2(*(__half2*)&pv.x, *(__half2*)&qv.x), z);
        __half2 s1 = __hmax2(__hadd2(*(__half2*)&pv.y, *(__half2*)&qv.y), z);
        __half2 s2 = __hmax2(__hadd2(*(__half2*)&pv.z, *(__half2*)&qv.z), z);
        __half2 s3 = __hmax2(__hadd2(*(__half2*)&pv.w, *(__half2*)&qv.w), z);

        float2 f0 = __half22float2(s0);
        float2 f1 = __half22float2(s1);
        float2 f2 = __half22float2(s2);
        float2 f3 = __half22float2(s3);

        float p = f0.x * w2a.x;
        p = fmaf(f0.y, w2a.y, p);
        p = fmaf(f1.x, w2a.z, p);
        p = fmaf(f1.y, w2a.w, p);
        p = fmaf(f2.x, w2b.x, p);
        p = fmaf(f2.y, w2b.y, p);
        p = fmaf(f3.x, w2b.z, p);
        p = fmaf(f3.y, w2b.w, p);
        #pragma unroll
        for (int o = 8; o > 0; o >>= 1) p += __shfl_xor_sync(0xFFFFFFFFu, p, o);
        if (lane16 == 0) {
            float ex = expf(p + b2v);
            g_exps[e] = ex;
            s += ex;
        }
    }

    sdata[threadIdx.x] = s;
    __syncthreads();
    for (int o = 128; o > 0; o >>= 1) {
        if (threadIdx.x < o) sdata[threadIdx.x] += sdata[threadIdx.x + o];
        __syncthreads();
    }
    if (threadIdx.x == 0) {
        g_partials[blockIdx.x] = sdata[0];
        __threadfence();
        int old = atomicAdd(&g_done, 1);
        is_last = (old == EDGE_BLOCKS - 1) ? 1 : 0;
    }
    __syncthreads();
    if (is_last) {
        float t = 0.f;
        for (int i = threadIdx.x; i < EDGE_BLOCKS; i += 256) t += g_partials[i];
        sdata[threadIdx.x] = t;
        __syncthreads();
        for (int o = 128; o > 0; o >>= 1) {
            if (threadIdx.x < o) sdata[threadIdx.x] += sdata[threadIdx.x + o];
            __syncthreads();
        }
        if (threadIdx.x == 0) {
            g_inv_total = 1.f / sdata[0];
            g_done = 0;   // reset for graph replay
        }
    }
}

__global__ void k_norm(float4* __restrict__ out, int n4) {
    int i = blockIdx.x * blockDim.x + threadIdx.x;
    if (i < n4) {
        float inv = g_inv_total;
        float4 v = ((const float4*)g_exps)[i];
        out[i] = make_float4(v.x * inv, v.y * inv, v.z * inv, v.w * inv);
    }
}
__global__ void k_norm_tail(float* __restrict__ out, int start, int E) {
    int i = start + blockIdx.x * blockDim.x + threadIdx.x;
    if (i < E) out[i] = g_exps[i] * g_inv_total;
}

extern "C" void kernel_launch(void* const* d_in, const int* in_sizes, int n_in,
                              void* d_out, int out_size) {
    const float* emb = (const float*)d_in[0];
    const int*   lm  = (const int*)d_in[1];
    const float* W1  = (const float*)d_in[2];
    const float* b1  = (const float*)d_in[3];
    const float* W2  = (const float*)d_in[4];
    const float* b2  = (const float*)d_in[5];
    float* out = (float*)d_out;
    const int E      = in_sizes[1] / 2;
    const int nodes  = in_sizes[0] / 128;
    const int ntiles = (nodes + 127) / 128;

    cudaFuncSetAttribute(k_node, cudaFuncAttributeMaxDynamicSharedMemorySize, NODE_SMEM);

    k_prep<<<128, 256>>>(W1);
    k_node<<<296, 256, NODE_SMEM>>>(emb, b1, nodes, ntiles);
    k_edge<<<EDGE_BLOCKS, 256>>>(lm, W2, b2, E);
    const int n4 = E >> 2;
    if (n4 > 0) k_norm<<<(n4 + 255) / 256, 256>>>((float4*)out, n4);
    if (E & 3) k_norm_tail<<<1, 256>>>(out, n4 << 2, E);
}

// round 14
// speedup vs baseline: 13.8659x; 1.0046x over previous
#include <cuda_runtime.h>
#include <cuda_fp16.h>
#include <cstdint>

// RelationalPolicyHead, factored:
//   W1T fp16 pre-transposed once                      [k_prep]
//   P = emb @ U, Q = emb @ V + b1                     [k_node: persistent HMMA, ldmatrix A+B]
//   e_exp = exp( W2^T relu(P[src]+Q'[tgt]) + b2 )     [k_edge: half-warp per EDGE PAIR, half2 math]
//   probs = e_exp * (1/total)                         [k_norm]

#define EDGE_BLOCKS 2048
#define MAX_NODES 100000
#define NSTR 136   // halves per smem row (272 B): conflict-free ldmatrix

__device__ __half g_Wt[2 * 128 * 128];   // [half][n][k] fp16
__device__ __half g_Ph[MAX_NODES * 128];
__device__ __half g_Qh[MAX_NODES * 128];
__device__ float  g_exps[1048576];
__device__ float  g_partials[EDGE_BLOCKS];
__device__ float  g_inv_total;
__device__ int    g_done = 0;

__device__ __forceinline__ uint32_t smem_u32(const void* p) {
    uint32_t a;
    asm("{ .reg .u64 t; cvta.to.shared.u64 t, %1; cvt.u32.u64 %0, t; }" : "=r"(a) : "l"(p));
    return a;
}

// ---------------- W1 -> fp16 transposed [h][n][k] ----------------
__global__ void k_prep(const float* __restrict__ W1) {
    int i = blockIdx.x * 256 + threadIdx.x;          // 32768
    int h = i >> 14, r = i & 16383;
    int n = r >> 7, k = r & 127;
    g_Wt[i] = __float2half_rn(W1[h * 16384 + k * 128 + n]);
}

// ---------------- node GEMM: persistent, mma.sync m16n8k16 ----------------
#define NODE_SMEM (2 * 128 * NSTR * 2 + 512)   // As + Bs fp16 + b1f

__global__ __launch_bounds__(256, 2)
void k_node(const float* __restrict__ emb, const float* __restrict__ b1,
            int nodes, int ntiles) {
    extern __shared__ __half hsm[];
    __half* As = hsm;                 // [m][k] 128 x NSTR
    __half* Bs = hsm + 128 * NSTR;    // [n][k] 128 x NSTR
    float*  b1f = (float*)(hsm + 2 * 128 * NSTR);

    const int tid  = threadIdx.x;
    const int lane = tid & 31;
    const int w    = tid >> 5;
    const int by   = blockIdx.x & 1;          // 0 -> U/P, 1 -> V/Q(+b1)
    const int t0   = blockIdx.x >> 1;

    {
        const uint4* src = (const uint4*)(g_Wt + by * 16384);
        #pragma unroll
        for (int it = 0; it < 8; it++) {
            int i = it * 256 + tid;
            int r = i >> 4, c8 = (i & 15) * 8;
            *(uint4*)(Bs + r * NSTR + c8) = src[i];
        }
        if (tid < 128) b1f[tid] = by ? b1[tid] : 0.f;
    }

    const uint32_t as_base = smem_u32(As);
    const uint32_t bs_base = smem_u32(Bs);

    const int bmat = lane >> 3, bs_ = lane & 7;
    const uint32_t brow_off = (uint32_t)((((bmat >> 1) * 8 + bs_) * NSTR + (bmat & 1) * 8) * 2);
    const int arow = (lane & 7) + ((lane >> 3) & 1) * 8;
    const int acol8 = (lane >> 4) * 8;

    __half* out = by ? g_Qh : g_Ph;

    for (int t = t0; t < ntiles; t += 148) {
        const int m0 = t * 128;

        __syncthreads();
        #pragma unroll
        for (int it = 0; it < 16; it++) {
            int i4 = it * 256 + tid;
            int row = i4 >> 5, c4 = (i4 & 31) * 4;
            float4 v = make_float4(0.f, 0.f, 0.f, 0.f);
            if (m0 + row < nodes) v = ((const float4*)emb)[(size_t)(m0 + row) * 32 + (i4 & 31)];
            __half2 h01 = __floats2half2_rn(v.x, v.y);
            __half2 h23 = __floats2half2_rn(v.z, v.w);
            uint2 pk;
            pk.x = *(uint32_t*)&h01; pk.y = *(uint32_t*)&h23;
            *(uint2*)(As + row * NSTR + c4) = pk;
        }
        __syncthreads();

        float acc[16][4];
        #pragma unroll
        for (int i = 0; i < 16; i++)
            #pragma unroll
            for (int j = 0; j < 4; j++) acc[i][j] = 0.f;

        #pragma unroll
        for (int kc = 0; kc < 8; kc++) {
            uint32_t a0, a1, a2, a3;
            uint32_t aaddr = as_base + (uint32_t)(((w * 16 + arow) * NSTR) + kc * 16 + acol8) * 2u;
            asm volatile("ldmatrix.sync.aligned.m8n8.x4.shared.b16 {%0,%1,%2,%3}, [%4];"
                         : "=r"(a0), "=r"(a1), "=r"(a2), "=r"(a3) : "r"(aaddr));

            #pragma unroll
            for (int g = 0; g < 8; g++) {
                uint32_t baddr = bs_base + brow_off
                               + (uint32_t)(g * 16 * NSTR + kc * 16) * 2u;
                uint32_t b0, b1r, b2, b3;
                asm volatile("ldmatrix.sync.aligned.m8n8.x4.shared.b16 {%0,%1,%2,%3}, [%4];"
                             : "=r"(b0), "=r"(b1r), "=r"(b2), "=r"(b3) : "r"(baddr));
                asm volatile(
                    "mma.sync.aligned.m16n8k16.row.col.f32.f16.f16.f32 "
                    "{%0,%1,%2,%3}, {%4,%5,%6,%7}, {%8,%9}, {%0,%1,%2,%3};"
                    : "+f"(acc[2*g][0]), "+f"(acc[2*g][1]), "+f"(acc[2*g][2]), "+f"(acc[2*g][3])
                    : "r"(a0), "r"(a1), "r"(a2), "r"(a3), "r"(b0), "r"(b1r));
                asm volatile(
                    "mma.sync.aligned.m16n8k16.row.col.f32.f16.f16.f32 "
                    "{%0,%1,%2,%3}, {%4,%5,%6,%7}, {%8,%9}, {%0,%1,%2,%3};"
                    : "+f"(acc[2*g+1][0]), "+f"(acc[2*g+1][1]), "+f"(acc[2*g+1][2]), "+f"(acc[2*g+1][3])
                    : "r"(a0), "r"(a1), "r"(a2), "r"(a3), "r"(b2), "r"(b3));
            }
        }

        const int r0 = m0 + w * 16 + (lane >> 2);
        const int cb = (lane & 3) * 2;
        if (r0 < nodes) {
            #pragma unroll
            for (int n8 = 0; n8 < 16; n8++) {
                float bx = b1f[n8 * 8 + cb], by2 = b1f[n8 * 8 + cb + 1];
                __half2 h = __floats2half2_rn(acc[n8][0] + bx, acc[n8][1] + by2);
                *(uint32_t*)(out + (size_t)r0 * 128 + n8 * 8 + cb) = *(uint32_t*)&h;
            }
        }
        if (r0 + 8 < nodes) {
            #pragma unroll
            for (int n8 = 0; n8 < 16; n8++) {
                float bx = b1f[n8 * 8 + cb], by2 = b1f[n8 * 8 + cb + 1];
                __half2 h = __floats2half2_rn(acc[n8][2] + bx, acc[n8][3] + by2);
                *(uint32_t*)(out + (size_t)(r0 + 8) * 128 + n8 * 8 + cb) = *(uint32_t*)&h;
            }
        }
    }
}

// ---------------- edge kernel: half-warp per edge PAIR (MLP=4), fused exp + sum ----------------
__global__ __launch_bounds__(256)
void k_edge(const int* __restrict__ lm, const float* __restrict__ W2,
            const float* __restrict__ b2, int E) {
    __shared__ float sdata[256];
    __shared__ int   is_last;
    const int lane   = threadIdx.x & 31;
    const int lane16 = lane & 15;
    const int hw     = ((blockIdx.x * 256 + threadIdx.x) >> 5) * 2 + (lane >> 4);
    const int nhw    = (EDGE_BLOCKS * 256) >> 4;

    const float4 w2a = ((const float4*)W2)[lane16 * 2];
    const float4 w2b = ((const float4*)W2)[lane16 * 2 + 1];
    const float  b2v = b2[0];
    const __half2 z  = __float2half2_rn(0.f);

    const int npairs = (E + 1) >> 1;
    float s = 0.f;
    for (int pi = hw; pi < npairs; pi += nhw) {
        const int e0 = pi * 2;
        const bool has1 = (e0 + 1) < E;

        // issue all 4 index loads, then all 4 row loads (MLP=4)
        int sn0 = lm[e0];
        int tn0 = lm[E + e0];
        int sn1 = has1 ? lm[e0 + 1] : sn0;
        int tn1 = has1 ? lm[E + e0 + 1] : tn0;

        uint4 pv0 = *(const uint4*)(g_Ph + (size_t)sn0 * 128 + lane16 * 8);
        uint4 qv0 = *(const uint4*)(g_Qh + (size_t)tn0 * 128 + lane16 * 8);
        uint4 pv1 = *(const uint4*)(g_Ph + (size_t)sn1 * 128 + lane16 * 8);
        uint4 qv1 = *(const uint4*)(g_Qh + (size_t)tn1 * 128 + lane16 * 8);

        __half2 a0 = __hmax2(__hadd2(*(__half2*)&pv0.x, *(__half2*)&qv0.x), z);
        __half2 a1 = __hmax2(__hadd2(*(__half2*)&pv0.y, *(__half2*)&qv0.y), z);
        __half2 a2 = __hmax2(__hadd2(*(__half2*)&pv0.z, *(__half2*)&qv0.z), z);
        __half2 a3 = __hmax2(__hadd2(*(__half2*)&pv0.w, *(__half2*)&qv0.w), z);
        __half2 c0 = __hmax2(__hadd2(*(__half2*)&pv1.x, *(__half2*)&qv1.x), z);
        __half2 c1 = __hmax2(__hadd2(*(__half2*)&pv1.y, *(__half2*)&qv1.y), z);
        __half2 c2 = __hmax2(__hadd2(*(__half2*)&pv1.z, *(__half2*)&qv1.z), z);
        __half2 c3 = __hmax2(__hadd2(*(__half2*)&pv1.w, *(__half2*)&qv1.w), z);

        float2 f0 = __half22float2(a0), f1 = __half22float2(a1);
        float2 f2 = __half22float2(a2), f3 = __half22float2(a3);
        float2 g0 = __half22float2(c0), g1 = __half22float2(c1);
        float2 g2 = __half22float2(c2), g3 = __half22float2(c3);

        float p = f0.x * w2a.x;
        float q = g0.x * w2a.x;
        p = fmaf(f0.y, w2a.y, p);  q = fmaf(g0.y, w2a.y, q);
        p = fmaf(f1.x, w2a.z, p);  q = fmaf(g1.x, w2a.z, q);
        p = fmaf(f1.y, w2a.w, p);  q = fmaf(g1.y, w2a.w, q);
        p = fmaf(f2.x, w2b.x, p);  q = fmaf(g2.x, w2b.x, q);
        p = fmaf(f2.y, w2b.y, p);  q = fmaf(g2.y, w2b.y, q);
        p = fmaf(f3.x, w2b.z, p);  q = fmaf(g3.x, w2b.z, q);
        p = fmaf(f3.y, w2b.w, p);  q = fmaf(g3.y, w2b.w, q);

        #pragma unroll
        for (int o = 8; o > 0; o >>= 1) {
            p += __shfl_xor_sync(0xFFFFFFFFu, p, o);
            q += __shfl_xor_sync(0xFFFFFFFFu, q, o);
        }
        if (lane16 == 0) {
            float ex0 = expf(p + b2v);
            g_exps[e0] = ex0;
            s += ex0;
            if (has1) {
                float ex1 = expf(q + b2v);
                g_exps[e0 + 1] = ex1;
                s += ex1;
            }
        }
    }

    sdata[threadIdx.x] = s;
    __syncthreads();
    for (int o = 128; o > 0; o >>= 1) {
        if (threadIdx.x < o) sdata[threadIdx.x] += sdata[threadIdx.x + o];
        __syncthreads();
    }
    if (threadIdx.x == 0) {
        g_partials[blockIdx.x] = sdata[0];
        __threadfence();
        int old = atomicAdd(&g_done, 1);
        is_last = (old == EDGE_BLOCKS - 1) ? 1 : 0;
    }
    __syncthreads();
    if (is_last) {
        float t = 0.f;
        for (int i = threadIdx.x; i < EDGE_BLOCKS; i += 256) t += g_partials[i];
        sdata[threadIdx.x] = t;
        __syncthreads();
        for (int o = 128; o > 0; o >>= 1) {
            if (threadIdx.x < o) sdata[threadIdx.x] += sdata[threadIdx.x + o];
            __syncthreads();
        }
        if (threadIdx.x == 0) {
            g_inv_total = 1.f / sdata[0];
            g_done = 0;   // reset for graph replay
        }
    }
}

__global__ void k_norm(float4* __restrict__ out, int n4) {
    int i = blockIdx.x * blockDim.x + threadIdx.x;
    if (i < n4) {
        float inv = g_inv_total;
        float4 v = ((const float4*)g_exps)[i];
        out[i] = make_float4(v.x * inv, v.y * inv, v.z * inv, v.w * inv);
    }
}
__global__ void k_norm_tail(float* __restrict__ out, int start, int E) {
    int i = start + blockIdx.x * blockDim.x + threadIdx.x;
    if (i < E) out[i] = g_exps[i] * g_inv_total;
}

extern "C" void kernel_launch(void* const* d_in, const int* in_sizes, int n_in,
                              void* d_out, int out_size) {
    const float* emb = (const float*)d_in[0];
    const int*   lm  = (const int*)d_in[1];
    const float* W1  = (const float*)d_in[2];
    const float* b1  = (const float*)d_in[3];
    const float* W2  = (const float*)d_in[4];
    const float* b2  = (const float*)d_in[5];
    float* out = (float*)d_out;
    const int E      = in_sizes[1] / 2;
    const int nodes  = in_sizes[0] / 128;
    const int ntiles = (nodes + 127) / 128;

    cudaFuncSetAttribute(k_node, cudaFuncAttributeMaxDynamicSharedMemorySize, NODE_SMEM);

    k_prep<<<128, 256>>>(W1);
    k_node<<<296, 256, NODE_SMEM>>>(emb, b1, nodes, ntiles);
    k_edge<<<EDGE_BLOCKS, 256>>>(lm, W2, b2, E);
    const int n4 = E >> 2;
    if (n4 > 0) k_norm<<<(n4 + 255) / 256, 256>>>((float4*)out, n4);
    if (E & 3) k_norm_tail<<<1, 256>>>(out, n4 << 2, E);
}